// round 14
// baseline (speedup 1.0000x reference)
#include <cuda_runtime.h>
#include <cstdint>

#define TT   32
#define BB   16
#define INS  64
#define OUTS 64
#define LL   4096
#define WW   64
#define CO   332      // OUT + 70 + 198
#define NBLK 128
#define NTHR 512
#define CHUNK 512

// ---- smem layout (float offsets) ----
#define S_MEM  0        // 64*512 memory slice [w][l]  (init: x staging at front)
#define S_WUP  32768    // 2×512 wur ping-pong (unnormalized)
#define S_WWP  33792    // 2×512 wuw ping-pong (unnormalized)
#define S_ER   34816    // 512 exp read
#define S_EW   35328    // 512 exp write
#define S_EAP  35840    // 128 pending packed (e,a) per w  (step t-1's)
#define S_KEY  35968    // 128 packed (kr,kw) per w
#define S_CAT  36096    // 128 cat = [out_{t-1} | r_{t-1}]
#define S_SCR  36224    // 512 scratch: reductions 0..47; co at +128..459; scal 464..
#define S_PAR  36736    // 288 params (+280/281: inv_sr_prev / inv_sw_prev)
#define S_COX  37024    // 32*332 precomputed x@Wc + bc (full, per block)
#define S_TOT  47648    // floats -> 190592 bytes

// ---------------- persistent device state ----------------
__device__ float g_WcT[CO*192];                   // transposed controller weights
// val2: [0]=s_er_p [1]=s_ew_p [2]=er0 [3]=er511 [4]=ew0 [5]=ew511        (tick2)
// val4 x2: [0]=s_wur_p [1]=s_wuw_p [2]=wur0 [3]=wur511 [4]=wuw0 [5]=wuw511
//          [16..79]=rparts[64] (ALL UNNORMALIZED)                         (tick4)
__device__ __align__(128) float g_val2[BB][8][8];
__device__ __align__(128) float g_val4[2][BB][8][96];
__device__ __align__(128) unsigned g_tick2[BB][32];
__device__ __align__(128) unsigned g_tick4[BB][32];
// init barrier (sense-reversal; safe for ANY initial state + graph replay)
__device__ __align__(128) unsigned g_bcnt[BB*32];
__device__ __align__(128) unsigned g_bgen[BB*32];

__device__ __forceinline__ float softplusf(float x) {
    return (x > 20.f) ? x : log1pf(__expf(x));
}
__device__ __forceinline__ float sigmoidf(float x) {
    return 1.f / (1.f + __expf(-x));
}
__device__ __forceinline__ unsigned ldcg_u(const unsigned* p) {
    unsigned v; asm volatile("ld.global.cg.u32 %0, [%1];" : "=r"(v) : "l"(p)); return v;
}
__device__ __forceinline__ float ldcg_f(const float* p) {
    float v; asm volatile("ld.global.cg.f32 %0, [%1];" : "=f"(v) : "l"(p)); return v;
}
__device__ __forceinline__ void stcg_u(unsigned* p, unsigned v) {
    asm volatile("st.global.cg.u32 [%0], %1;" :: "l"(p), "r"(v) : "memory");
}
__device__ __forceinline__ void stcg_f(float* p, float v) {
    asm volatile("st.global.cg.f32 [%0], %1;" :: "l"(p), "f"(v) : "memory");
}
__device__ __forceinline__ void stcg_f4(float* p, float4 v) {
    asm volatile("st.global.cg.v4.f32 [%0], {%1,%2,%3,%4};"
                 :: "l"(p), "f"(v.x), "f"(v.y), "f"(v.z), "f"(v.w) : "memory");
}

// 8-block sense-reversal barrier (init only). Robust to arbitrary initial
// tick state: count self-resets, gen strictly increases within a launch.
__device__ __forceinline__ void groupbar(int grp, int tid) {
    __syncthreads();
    if (tid == 0) {
        __threadfence();
        const int idx = grp * 32;
        unsigned gen  = *(volatile unsigned*)&g_bgen[idx];
        unsigned prev = atomicAdd(&g_bcnt[idx], 1u);
        if (prev == 7u) {
            atomicExch(&g_bcnt[idx], 0u);
            __threadfence();
            atomicAdd(&g_bgen[idx], 1u);
        } else {
            while (*(volatile unsigned*)&g_bgen[idx] == gen) { __nanosleep(64); }
        }
        __threadfence();
    }
    __syncthreads();
}

// Poll 8 tickets for exact value `want` (lanes 0..7 of warp 0), then block-sync.
__device__ __forceinline__ void poll8(const unsigned* ticks, unsigned want, int tid) {
    if (tid < 8) {
        int n = 0;
        while (ldcg_u(&ticks[tid]) != want) { if (++n > 64) __nanosleep(32); }
    }
    __syncthreads();
}

__global__ __launch_bounds__(NTHR)
void ntm_kernel(const float* __restrict__ x, const float* __restrict__ Wc,
                const float* __restrict__ bc, float* __restrict__ dout)
{
    extern __shared__ __align__(16) float sh[];
    const int tid   = threadIdx.x;
    const int warp  = tid >> 5;
    const int lane  = tid & 31;
    const int b     = blockIdx.x >> 3;   // batch
    const int chunk = blockIdx.x & 7;
    const int l0    = chunk * CHUNK;
    float* P    = sh + S_PAR;
    float* co   = sh + S_SCR + 128;
    float* scal = sh + S_SCR + 464;

    // ================= init =================
    {
        if (tid == 0) stcg_u(&g_tick2[b][chunk], 0u);   // replay-safe reset

        // WcT slice: rows i in [chunk*24, chunk*24+24)
        for (int idx = tid; idx < 24*CO; idx += NTHR) {
            const int i = chunk*24 + idx / CO;
            const int j = idx % CO;
            stcg_f(&g_WcT[j*192 + i], __ldg(&Wc[i*CO + j]));
        }
        // REAL barrier (initial-state independent): WcT complete before coX
        groupbar(b, tid);

        // stage x for this batch into front of S_MEM (zeroed afterwards)
        for (int idx = tid; idx < TT*INS; idx += NTHR) {
            const int t = idx >> 6, i = idx & 63;
            sh[S_MEM + idx] = __ldg(&x[(t*BB + b)*INS + i]);
        }
        __syncthreads();
        // coX[t][j] = bc[j] + x[t] @ WcT[j][0:64]  — FULL 332 per block
        for (int item = tid; item < CO*4; item += NTHR) {
            const int j = item >> 2, tg = item & 3;
            const float bj = __ldg(&bc[j]);
            float acc[8];
            #pragma unroll
            for (int k = 0; k < 8; ++k) acc[k] = bj;
            #pragma unroll 4
            for (int q = 0; q < 16; ++q) {
                const float4 w = *(const float4*)(g_WcT + j*192 + q*4);
                #pragma unroll
                for (int k = 0; k < 8; ++k) {
                    const float* xr = sh + S_MEM + (tg*8 + k)*64 + q*4;
                    acc[k] = fmaf(w.x, xr[0], acc[k]);
                    acc[k] = fmaf(w.y, xr[1], acc[k]);
                    acc[k] = fmaf(w.z, xr[2], acc[k]);
                    acc[k] = fmaf(w.w, xr[3], acc[k]);
                }
            }
            #pragma unroll
            for (int k = 0; k < 8; ++k)
                sh[S_COX + (tg*8 + k)*CO + j] = acc[k];
        }
        __syncthreads();
        // zero memory slice (x staging overwritten)
        float4* m4 = (float4*)(sh + S_MEM);
        for (int i = tid; i < WW*CHUNK/4; i += NTHR) m4[i] = make_float4(0,0,0,0);
        // ping buffer 1 = initial w (unnormalized delta); EAP=0 -> identity update
        for (int k = tid; k < CHUNK; k += NTHR) {
            const float d = (l0 + k == 0) ? 1.f : 0.f;
            sh[S_WUP + 512 + k] = d;
            sh[S_WWP + 512 + k] = d;
        }
        if (tid < 128) sh[S_EAP + tid] = 0.f;
        if (tid < 64)  sh[S_CAT + tid] = 0.f;           // out_{-1} = 0
        // initial val4 buffer 1: rparts=0, sums/halos = delta pattern
        if (tid < 16) {
            stcg_f4(&g_val4[1][b][chunk][16 + 4*tid], make_float4(0,0,0,0));
            __threadfence();
        } else if (tid == 16) {
            const float d0 = (l0 == 0) ? 1.f : 0.f;
            stcg_f4(&g_val4[1][b][chunk][0], make_float4(d0, d0, d0, 0.f));
            stcg_f4(&g_val4[1][b][chunk][4], make_float4(d0, 0.f, 0.f, 0.f));
            __threadfence();
        }
        __syncthreads();
        if (tid == 0) stcg_u(&g_tick4[b][chunk], 0u);
    }

    for (int t = 0; t < TT; ++t) {
        const int pb4 = (t & 1) ^ 1;     // prev-step buffers
        const int cb  = t & 1;           // current-step buffers

        // ===== Phase A: poll end-of-prev-step mailbox; r + inv sums ========
        poll8(g_tick4[b], (unsigned)t, tid);
        if (warp == 0 && lane < 8) {
            float swr = ldcg_f(&g_val4[pb4][b][lane][0]);
            float sww = ldcg_f(&g_val4[pb4][b][lane][1]);
            #pragma unroll
            for (int o = 4; o; o >>= 1) {
                swr += __shfl_xor_sync(0xffu, swr, o, 8);
                sww += __shfl_xor_sync(0xffu, sww, o, 8);
            }
            if (lane == 0) { P[280] = 1.f/swr; P[281] = 1.f/sww; }
        } else if (tid >= 64 && tid < 128) {
            const int i = tid - 64;
            float s = 0.f;
            #pragma unroll
            for (int k = 0; k < 8; ++k) s += ldcg_f(&g_val4[pb4][b][k][16 + i]);
            sh[S_CAT + 64 + i] = s;                      // raw r
        }
        __syncthreads();
        if (tid < 64) sh[S_CAT + 64 + tid] *= P[280];    // normalize r
        __syncthreads();

        // ===== Phase B: GEMM part A — urgent params columns j in [64,204) ===
        if (tid < 288) {
            const int jl = tid >> 1, half = tid & 1;
            const int jc = (jl < 140) ? jl : 139;
            const int j  = 64 + jc;
            const float4* wp = (const float4*)(g_WcT + j*192 + 64 + half*64);
            const float4* cp = (const float4*)(sh + S_CAT + half*64);
            float acc = half ? 0.f : sh[S_COX + t*CO + j];
            #pragma unroll 8
            for (int q = 0; q < 16; ++q) {
                const float4 w = __ldg(wp + q);
                const float4 c = cp[q];
                acc = fmaf(w.x, c.x, acc); acc = fmaf(w.y, c.y, acc);
                acc = fmaf(w.z, c.z, acc); acc = fmaf(w.w, c.w, acc);
            }
            acc += __shfl_xor_sync(0xffffffffu, acc, 1);
            if (!half && jl < 140) co[j] = acc;
        }
        __syncthreads();

        // ===== Phase C: key norms + params (parallelized) ===================
        if (warp == 0) {            // ||k_r||^2
            float p = co[64+lane]*co[64+lane] + co[96+lane]*co[96+lane];
            #pragma unroll
            for (int o = 16; o; o >>= 1) p += __shfl_xor_sync(0xffffffffu, p, o);
            if (lane == 0) scal[14] = p;
        } else if (warp == 1) {     // ||k_w||^2
            float p = co[134+lane]*co[134+lane] + co[166+lane]*co[166+lane];
            #pragma unroll
            for (int o = 16; o; o >>= 1) p += __shfl_xor_sync(0xffffffffu, p, o);
            if (lane == 0) scal[15] = p;
        }
        __syncthreads();
        if (tid == 0) {
            const float beta_r = softplusf(co[128]);
            scal[0] = beta_r * rsqrtf(scal[14] + 1e-14f);
            P[128] = beta_r;
            P[129] = sigmoidf(co[129]);
            P[130] = softplusf(co[130]) + 1.f;
        } else if (tid == 32) {
            const float m = fmaxf(co[131], fmaxf(co[132], co[133]));
            const float e0=__expf(co[131]-m), e1=__expf(co[132]-m), e2=__expf(co[133]-m);
            const float inv = 1.f/(e0+e1+e2);
            P[131]=e0*inv; P[132]=e1*inv; P[133]=e2*inv;
        } else if (tid == 64) {
            const float beta_w = softplusf(co[198]);
            scal[1] = beta_w * rsqrtf(scal[15] + 1e-14f);
            P[134] = beta_w;
            P[135] = sigmoidf(co[199]);
            P[136] = softplusf(co[200]) + 1.f;
        } else if (tid == 96) {
            const float m = fmaxf(co[201], fmaxf(co[202], co[203]));
            const float e0=__expf(co[201]-m), e1=__expf(co[202]-m), e2=__expf(co[203]-m);
            const float inv = 1.f/(e0+e1+e2);
            P[137]=e0*inv; P[138]=e1*inv; P[139]=e2*inv;
        }
        __syncthreads();
        if (tid < 64) {
            sh[S_KEY + 2*tid]     = co[64 + tid]  * scal[0];
            sh[S_KEY + 2*tid + 1] = co[134 + tid] * scal[1];
        }
        __syncthreads();

        // ===== Phase D: fused lazy update + cosine similarity ===============
        if (tid < 128) {
            const float beta_r = P[128], beta_w = P[134];
            const float iswp = P[281];
            const float4 wu = *(const float4*)(sh + S_WWP + pb4*512 + 4*tid);
            const float4 wn = make_float4(wu.x*iswp, wu.y*iswp, wu.z*iswp, wu.w*iswp);
            float4 dr = make_float4(0,0,0,0), dw = dr, ds = dr;
            #pragma unroll 8
            for (int w = 0; w < WW; ++w) {
                float4* mp = (float4*)(sh + S_MEM + w*CHUNK + 4*tid);
                float4 m = *mp;
                const float2 ea = *(const float2*)(sh + S_EAP + 2*w);
                m.x = fmaf(wn.x, fmaf(-m.x, ea.x, ea.y), m.x);   // lazy write (t-1)
                m.y = fmaf(wn.y, fmaf(-m.y, ea.x, ea.y), m.y);
                m.z = fmaf(wn.z, fmaf(-m.z, ea.x, ea.y), m.z);
                m.w = fmaf(wn.w, fmaf(-m.w, ea.x, ea.y), m.w);
                *mp = m;
                const float2 kk = *(const float2*)(sh + S_KEY + 2*w);
                dr.x = fmaf(m.x,kk.x,dr.x); dr.y = fmaf(m.y,kk.x,dr.y);
                dr.z = fmaf(m.z,kk.x,dr.z); dr.w = fmaf(m.w,kk.x,dr.w);
                dw.x = fmaf(m.x,kk.y,dw.x); dw.y = fmaf(m.y,kk.y,dw.y);
                dw.z = fmaf(m.z,kk.y,dw.z); dw.w = fmaf(m.w,kk.y,dw.w);
                ds.x = fmaf(m.x,m.x,ds.x); ds.y = fmaf(m.y,m.y,ds.y);
                ds.z = fmaf(m.z,m.z,ds.z); ds.w = fmaf(m.w,m.w,ds.w);
            }
            float4 er, ew;
            {
                const float i0 = rsqrtf(ds.x + 1e-14f), i1 = rsqrtf(ds.y + 1e-14f);
                const float i2 = rsqrtf(ds.z + 1e-14f), i3 = rsqrtf(ds.w + 1e-14f);
                er.x = __expf(dr.x*i0 - beta_r); er.y = __expf(dr.y*i1 - beta_r);
                er.z = __expf(dr.z*i2 - beta_r); er.w = __expf(dr.w*i3 - beta_r);
                ew.x = __expf(dw.x*i0 - beta_w); ew.y = __expf(dw.y*i1 - beta_w);
                ew.z = __expf(dw.z*i2 - beta_w); ew.w = __expf(dw.w*i3 - beta_w);
            }
            *(float4*)(sh + S_ER + 4*tid) = er;
            *(float4*)(sh + S_EW + 4*tid) = ew;
            float se = er.x + er.y + er.z + er.w;
            float sw = ew.x + ew.y + ew.z + ew.w;
            #pragma unroll
            for (int o = 16; o; o >>= 1) {
                se += __shfl_xor_sync(0xffffffffu, se, o);
                sw += __shfl_xor_sync(0xffffffffu, sw, o);
            }
            if (lane == 0) { sh[S_SCR + warp] = se; sh[S_SCR + 16 + warp] = sw; }
        }
        __syncthreads();

        // ===== Phase E/F: post tick2; GEMM part B in the sync shadow ========
        if (tid == 400) {           // idle in GEMM-B — posts the mailbox
            float a = 0.f, c = 0.f;
            #pragma unroll
            for (int i = 0; i < 4; ++i) { a += sh[S_SCR+i]; c += sh[S_SCR+16+i]; }
            stcg_f4(&g_val2[b][chunk][0],
                    make_float4(a, c, sh[S_ER+0], sh[S_ER+CHUNK-1]));
            stcg_f4(&g_val2[b][chunk][4],
                    make_float4(sh[S_EW+0], sh[S_EW+CHUNK-1], 0.f, 0.f));
            __threadfence();
            stcg_u(&g_tick2[b][chunk], (unsigned)(t+1));
        }
        if (tid < 384) {            // j in [0,64) u [204,332): out | e | a
            const int jl = tid >> 1, half = tid & 1;
            const int j  = (jl < 64) ? jl : 140 + jl;
            const float4* wp = (const float4*)(g_WcT + j*192 + 64 + half*64);
            const float4* cp = (const float4*)(sh + S_CAT + half*64);
            float acc = half ? 0.f : sh[S_COX + t*CO + j];
            #pragma unroll 8
            for (int q = 0; q < 16; ++q) {
                const float4 w = __ldg(wp + q);
                const float4 c = cp[q];
                acc = fmaf(w.x, c.x, acc); acc = fmaf(w.y, c.y, acc);
                acc = fmaf(w.z, c.z, acc); acc = fmaf(w.w, c.w, acc);
            }
            acc += __shfl_xor_sync(0xffffffffu, acc, 1);
            if (!half) co[j] = acc;
        }
        __syncthreads();
        if (tid < 64) {             // extract out, e, a
            const float o = co[tid];
            sh[S_CAT + tid] = o;                           // out_t for next cat
            if (chunk == 0) dout[(t*BB + b)*OUTS + tid] = o;
            sh[S_EAP + 2*tid]     = sigmoidf(co[204 + tid]);   // e_t (pending)
            sh[S_EAP + 2*tid + 1] = co[268 + tid];             // a_t (pending)
        }

        // ===== Phase G: poll er sums =======================================
        poll8(g_tick2[b], (unsigned)(t+1), tid);
        if (tid < 8) {
            float se  = ldcg_f(&g_val2[b][tid][0]);
            float sw2 = ldcg_f(&g_val2[b][tid][1]);
            #pragma unroll
            for (int o = 4; o; o >>= 1) {
                se  += __shfl_xor_sync(0xffu, se,  o, 8);
                sw2 += __shfl_xor_sync(0xffu, sw2, o, 8);
            }
            if (tid == 0) { sh[S_SCR + 40] = se; sh[S_SCR + 41] = sw2; }
        }
        __syncthreads();

        // ===== Phase H: gate + shift + sharpen =============================
        {
            const float inv_ser = 1.f / sh[S_SCR + 40];
            const float inv_sew = 1.f / sh[S_SCR + 41];
            const float inv_srp = P[280], inv_swp = P[281];
            const float gr  = P[129], gamr = P[130];
            const float sr0 = P[131], sr1 = P[132], sr2 = P[133];
            const float gw  = P[135], gamw = P[136];
            const float sw0 = P[137], sw1 = P[138], sw2 = P[139];
            const int prv = (chunk + 7) & 7, nxt = (chunk + 1) & 7;
            const int k = tid;
            const float* wupP = sh + S_WUP + pb4*512;
            const float* wwpP = sh + S_WWP + pb4*512;
            float cmr, cmw, pmr, pmw, cpr, cpw, ppr, ppw;
            if (k == 0) {
                cmr = ldcg_f(&g_val2[b][prv][3]); cmw = ldcg_f(&g_val2[b][prv][5]);
                pmr = ldcg_f(&g_val4[pb4][b][prv][3]) * inv_srp;
                pmw = ldcg_f(&g_val4[pb4][b][prv][5]) * inv_swp;
            } else {
                cmr = sh[S_ER + k-1];  cmw = sh[S_EW + k-1];
                pmr = wupP[k-1] * inv_srp; pmw = wwpP[k-1] * inv_swp;
            }
            if (k == CHUNK-1) {
                cpr = ldcg_f(&g_val2[b][nxt][2]); cpw = ldcg_f(&g_val2[b][nxt][4]);
                ppr = ldcg_f(&g_val4[pb4][b][nxt][2]) * inv_srp;
                ppw = ldcg_f(&g_val4[pb4][b][nxt][4]) * inv_swp;
            } else {
                cpr = sh[S_ER + k+1];  cpw = sh[S_EW + k+1];
                ppr = wupP[k+1] * inv_srp; ppw = wwpP[k+1] * inv_swp;
            }
            const float ccr = sh[S_ER + k],  pcr = wupP[k] * inv_srp;
            const float ccw = sh[S_EW + k],  pcw = wwpP[k] * inv_swp;
            float wgm = cmr*inv_ser*gr + (1.f-gr)*pmr;
            float wgc = ccr*inv_ser*gr + (1.f-gr)*pcr;
            float wgp = cpr*inv_ser*gr + (1.f-gr)*ppr;
            const float wur = powf(fmaxf(sr0*wgm + sr1*wgc + sr2*wgp, 0.f), gamr);
            wgm = cmw*inv_sew*gw + (1.f-gw)*pmw;
            wgc = ccw*inv_sew*gw + (1.f-gw)*pcw;
            wgp = cpw*inv_sew*gw + (1.f-gw)*ppw;
            const float wuw = powf(fmaxf(sw0*wgm + sw1*wgc + sw2*wgp, 0.f), gamw);
            sh[S_WUP + cb*512 + k] = wur;
            sh[S_WWP + cb*512 + k] = wuw;
            float ps_r = wur, ps_w = wuw;
            #pragma unroll
            for (int o = 16; o; o >>= 1) {
                ps_r += __shfl_xor_sync(0xffffffffu, ps_r, o);
                ps_w += __shfl_xor_sync(0xffffffffu, ps_w, o);
            }
            if (lane == 0) { sh[S_SCR + warp] = ps_r; sh[S_SCR + 16 + warp] = ps_w; }
        }
        __syncthreads();

        // ===== Phase I: unnormalized r-partials (current mem × wur) ========
        {
            float racc[4] = {0.f, 0.f, 0.f, 0.f};
            const int wbase = warp * 4;
            const float* wurP = sh + S_WUP + cb*512;
            #pragma unroll
            for (int kk = 0; kk < 4; ++kk) {
                const int j = lane + 32*kk;
                const float4 r = *(const float4*)(wurP + 4*j);
                #pragma unroll
                for (int w = 0; w < 4; ++w) {
                    const float4 m = *(const float4*)(sh + S_MEM + (wbase+w)*CHUNK + 4*j);
                    racc[w] += m.x*r.x + m.y*r.y + m.z*r.z + m.w*r.w;
                }
            }
            #pragma unroll
            for (int w = 0; w < 4; ++w) {
                #pragma unroll
                for (int o = 16; o; o >>= 1)
                    racc[w] += __shfl_xor_sync(0xffffffffu, racc[w], o);
                if (lane == 0) sh[S_SCR + 64 + wbase + w] = racc[w];
            }
        }
        __syncthreads();

        // ===== Phase J: single end-of-step mailbox post =====================
        if (tid < 16) {
            stcg_f4(&g_val4[cb][b][chunk][16 + 4*tid],
                    *(const float4*)(sh + S_SCR + 64 + 4*tid));
            __threadfence();
        } else if (tid == 16) {
            float psr = 0.f, psw = 0.f;
            #pragma unroll
            for (int i = 0; i < 16; ++i) { psr += sh[S_SCR+i]; psw += sh[S_SCR+16+i]; }
            stcg_f4(&g_val4[cb][b][chunk][0],
                    make_float4(psr, psw, sh[S_WUP+cb*512+0], sh[S_WUP+cb*512+CHUNK-1]));
            stcg_f4(&g_val4[cb][b][chunk][4],
                    make_float4(sh[S_WWP+cb*512+0], sh[S_WWP+cb*512+CHUNK-1], 0.f, 0.f));
            __threadfence();
        }
        __syncthreads();
        if (tid == 0) stcg_u(&g_tick4[b][chunk], (unsigned)(t+1));
    }
}

extern "C" void kernel_launch(void* const* d_in, const int* in_sizes, int n_in,
                              void* d_out, int out_size) {
    const float* x  = (const float*)d_in[0];   // (T,B,IN) fp32
    const float* Wc = (const float*)d_in[1];   // (192,332) fp32
    const float* bc = (const float*)d_in[2];   // (332,)   fp32
    static bool attr_done = false;
    if (!attr_done) {
        cudaFuncSetAttribute(ntm_kernel, cudaFuncAttributeMaxDynamicSharedMemorySize,
                             S_TOT * sizeof(float));
        attr_done = true;
    }
    ntm_kernel<<<NBLK, NTHR, S_TOT * sizeof(float)>>>(x, Wc, bc, (float*)d_out);
}

// round 17
// speedup vs baseline: 1.0240x; 1.0240x over previous
#include <cuda_runtime.h>
#include <cstdint>

#define TT   32
#define BB   16
#define INS  64
#define OUTS 64
#define LL   4096
#define WW   64
#define CO   332      // OUT + 70 + 198
#define NBLK 128
#define NTHR 512
#define CHUNK 512

// ---- smem layout (float offsets) ----
#define S_MEM  0        // 64*512 memory slice [w][l]
#define S_SWR  32768    // 512 normalized read w_prev
#define S_SWW  33280    // 512 normalized write w_prev
#define S_WWN  33792    // 512 PENDING normalized write weight (lazy update)
#define S_EAP  34304    // 128 pending packed (e,a) per w
#define S_KEY  34432    // 128 packed (kr,kw) per w
#define S_ER   34560    // 512 exp read    (init: x staging uses ER..WUW 2048)
#define S_EW   35072    // 512 exp write
#define S_WUR  35584    // 512 sharpened unnorm read
#define S_WUW  36096    // 512 sharpened unnorm write
#define S_SCR  36608    // 512 scratch: cat(128)+co(332)+scal(16); reductions
#define S_PAR  37120    // 288 params (+280/281: inv_sr_prev / inv_sw_prev)
#define S_COX  37408    // 32*332 = 10624 precomputed x@Wc + bc; row t also
                        // stores out_t after consumption
#define S_TOT  48032    // floats -> 192128 bytes  (37408 + 10624; FIXED)

// ---------------- persistent device state ----------------
__device__ float g_WcT[CO*192];                   // transposed controller weights
// val2: [0]=s_er [1]=s_ew [2]=er0 [3]=er511 [4]=ew0 [5]=ew511          (tick2)
// val3 x2: [0]=s_wur [1]=s_wuw [2]=wur0 [3]=wur511 [4]=wuw0 [5]=wuw511 (tick3)
// val4: [16..79]=rpart[64] (UNNORMALIZED)                               (tick4)
__device__ __align__(128) float g_val2[BB][8][8];
__device__ __align__(128) float g_val3[2][BB][8][8];
__device__ __align__(128) float g_val4[BB][8][96];
__device__ __align__(128) unsigned g_tick2[BB][32];
__device__ __align__(128) unsigned g_tick3[BB][32];
__device__ __align__(128) unsigned g_tick4[BB][32];

__device__ __forceinline__ float softplusf(float x) {
    return (x > 20.f) ? x : log1pf(__expf(x));
}
__device__ __forceinline__ float sigmoidf(float x) {
    return 1.f / (1.f + __expf(-x));
}
__device__ __forceinline__ unsigned ldcg_u(const unsigned* p) {
    unsigned v; asm volatile("ld.global.cg.u32 %0, [%1];" : "=r"(v) : "l"(p)); return v;
}
__device__ __forceinline__ float ldcg_f(const float* p) {
    float v; asm volatile("ld.global.cg.f32 %0, [%1];" : "=f"(v) : "l"(p)); return v;
}
__device__ __forceinline__ void stcg_u(unsigned* p, unsigned v) {
    asm volatile("st.global.cg.u32 [%0], %1;" :: "l"(p), "r"(v) : "memory");
}
__device__ __forceinline__ void stcg_f(float* p, float v) {
    asm volatile("st.global.cg.f32 [%0], %1;" :: "l"(p), "f"(v) : "memory");
}
__device__ __forceinline__ void stcg_f4(float* p, float4 v) {
    asm volatile("st.global.cg.v4.f32 [%0], {%1,%2,%3,%4};"
                 :: "l"(p), "f"(v.x), "f"(v.y), "f"(v.z), "f"(v.w) : "memory");
}

// Poll 8 tickets for exact value `want` (lanes 0..7 of warp 0), then block-sync.
__device__ __forceinline__ void poll8(const unsigned* ticks, unsigned want, int tid) {
    if (tid < 8) {
        int n = 0;
        while (ldcg_u(&ticks[tid]) != want) { if (++n > 64) __nanosleep(32); }
    }
    __syncthreads();
}

__global__ __launch_bounds__(NTHR)
void ntm_kernel(const float* __restrict__ x, const float* __restrict__ Wc,
                const float* __restrict__ bc, float* __restrict__ dout)
{
    extern __shared__ __align__(16) float sh[];
    const int tid   = threadIdx.x;
    const int warp  = tid >> 5;
    const int lane  = tid & 31;
    const int b     = blockIdx.x >> 3;   // batch
    const int chunk = blockIdx.x & 7;
    const int l0    = chunk * CHUNK;

    // ================= init =================
    {
        if (tid == 0) stcg_u(&g_tick2[b][chunk], 0u);   // replay-safe reset

        // WcT slice: rows i in [chunk*24, chunk*24+24)
        for (int idx = tid; idx < 24*CO; idx += NTHR) {
            const int i = chunk*24 + idx / CO;
            const int j = idx % CO;
            stcg_f(&g_WcT[j*192 + i], __ldg(&Wc[i*CO + j]));
        }
        __threadfence();
        __syncthreads();
        if (tid == 0) stcg_u(&g_tick3[b][chunk], 0u);   // WcT-done marker + reset
        poll8(g_tick3[b], 0u, tid);

        // stage x for this batch into ER..WUW scratch (2048 floats)
        for (int idx = tid; idx < TT*INS; idx += NTHR) {
            const int t = idx >> 6, i = idx & 63;
            sh[S_ER + idx] = __ldg(&x[(t*BB + b)*INS + i]);
        }
        __syncthreads();
        // coX[t][j] = bc[j] + x[t] @ WcT[j][0:64]
        if (tid < CO) {
            const float4* wp4 = (const float4*)(g_WcT + tid*192);
            const float bj = __ldg(&bc[tid]);
            #pragma unroll
            for (int th = 0; th < 4; th++) {
                float acc[8];
                #pragma unroll
                for (int k = 0; k < 8; k++) acc[k] = bj;
                #pragma unroll 4
                for (int q = 0; q < 16; q++) {
                    const float4 w = __ldg(wp4 + q);
                    #pragma unroll
                    for (int k = 0; k < 8; k++) {
                        const float* xr = sh + S_ER + (th*8 + k)*64 + q*4;
                        acc[k] = fmaf(w.x, xr[0], acc[k]);
                        acc[k] = fmaf(w.y, xr[1], acc[k]);
                        acc[k] = fmaf(w.z, xr[2], acc[k]);
                        acc[k] = fmaf(w.w, xr[3], acc[k]);
                    }
                }
                #pragma unroll
                for (int k = 0; k < 8; k++)
                    sh[S_COX + (th*8 + k)*CO + tid] = acc[k];
            }
        }
        __syncthreads();
        // zero memory slice (x staging overwritten)
        float4* m4 = (float4*)(sh + S_MEM);
        for (int i = tid; i < WW*CHUNK/4; i += NTHR) m4[i] = make_float4(0,0,0,0);
        for (int k = tid; k < CHUNK; k += NTHR) {
            const float v = (l0 + k == 0) ? 1.f : 0.f;
            sh[S_SWR + k] = v; sh[S_SWW + k] = v;
            sh[S_WWN + k] = 0.f;                     // no pending update at t=0
        }
        if (tid < 128) sh[S_EAP + tid] = 0.f;
        // initial mailbox state (all stores 16B-aligned)
        if (tid < 16) {
            stcg_f4(&g_val4[b][chunk][16 + 4*tid], make_float4(0,0,0,0)); // rpart=0
            __threadfence();
        } else if (tid == 16) {
            // val3 buffer 1 (read at t=0): [2]=wur0 [3]=wur511 [4]=wuw0 [5]=wuw511
            const float d0 = (l0 == 0) ? 1.f : 0.f;
            float* v3 = &g_val3[1][b][chunk][0];
            stcg_f4(v3,     make_float4(0.f, 0.f, d0, 0.f));
            stcg_f4(v3 + 4, make_float4(d0, 0.f, 0.f, 0.f));
            __threadfence();
        } else if (tid == 17) {
            sh[S_PAR + 280] = 1.f;   // inv_sr_prev
            sh[S_PAR + 281] = 1.f;   // inv_sw_prev
        }
        __syncthreads();
        if (tid == 0) stcg_u(&g_tick4[b][chunk], 0u);
    }

    for (int t = 0; t < TT; ++t) {
        float* P    = sh + S_PAR;
        float* co   = sh + S_SCR + 128;
        float* scal = sh + S_SCR + 464;
        const int pb = (t & 1) ^ 1;          // val3 buffer of step t-1

        // ===== Phase 1: poll rparts, r-sum, controller GEMM, params =====
        poll8(g_tick4[b], (unsigned)t, tid);
        if (tid < 64) {
            float s = 0.f;
            #pragma unroll
            for (int i = 0; i < 8; i++) s += ldcg_f(&g_val4[b][i][16 + tid]);
            // out_{t-1} was persisted into coX row t-1 after its consumption
            sh[S_SCR + tid]      = (t == 0) ? 0.f : sh[S_COX + (t-1)*CO + tid];
            sh[S_SCR + 64 + tid] = s * sh[S_PAR + 280];        // r_{t-1}
        }
        __syncthreads();
        if (tid < CO) {
            float acc0 = sh[S_COX + t*CO + tid], acc1 = 0.f;
            const float4* wp4  = (const float4*)(g_WcT + tid*192 + 64);
            const float4* cat4 = (const float4*)(sh + S_SCR);
            #pragma unroll 8
            for (int q = 0; q < 16; q++) {
                const float4 w0 = __ldg(wp4 + q);
                const float4 c0 = cat4[q];
                acc0 = fmaf(w0.x, c0.x, acc0); acc0 = fmaf(w0.y, c0.y, acc0);
                acc0 = fmaf(w0.z, c0.z, acc0); acc0 = fmaf(w0.w, c0.w, acc0);
                const float4 w1 = __ldg(wp4 + 16 + q);
                const float4 c1 = cat4[16 + q];
                acc1 = fmaf(w1.x, c1.x, acc1); acc1 = fmaf(w1.y, c1.y, acc1);
                acc1 = fmaf(w1.z, c1.z, acc1); acc1 = fmaf(w1.w, c1.w, acc1);
            }
            co[tid] = acc0 + acc1;
        }
        __syncthreads();
        if (warp == 0) {            // ||k_r||^2
            float p = co[64+lane]*co[64+lane] + co[96+lane]*co[96+lane];
            #pragma unroll
            for (int o = 16; o; o >>= 1) p += __shfl_xor_sync(0xffffffffu, p, o);
            if (lane == 0) scal[14] = p;
        } else if (warp == 1) {     // ||k_w||^2
            float p = co[134+lane]*co[134+lane] + co[166+lane]*co[166+lane];
            #pragma unroll
            for (int o = 16; o; o >>= 1) p += __shfl_xor_sync(0xffffffffu, p, o);
            if (lane == 0) scal[15] = p;
        }
        __syncthreads();
        if (tid == 0) {
            float beta_r = softplusf(co[128]);
            float beta_w = softplusf(co[198]);
            scal[0] = beta_r * rsqrtf(scal[14] + 1e-14f);
            scal[1] = beta_w * rsqrtf(scal[15] + 1e-14f);
            P[128] = beta_r;
            P[129] = sigmoidf(co[129]);
            P[130] = softplusf(co[130]) + 1.f;
            float m = fmaxf(co[131], fmaxf(co[132], co[133]));
            float e0=__expf(co[131]-m), e1=__expf(co[132]-m), e2=__expf(co[133]-m);
            float inv = 1.f/(e0+e1+e2);
            P[131]=e0*inv; P[132]=e1*inv; P[133]=e2*inv;
            P[134] = beta_w;
            P[135] = sigmoidf(co[199]);
            P[136] = softplusf(co[200]) + 1.f;
            m = fmaxf(co[201], fmaxf(co[202], co[203]));
            e0=__expf(co[201]-m); e1=__expf(co[202]-m); e2=__expf(co[203]-m);
            inv = 1.f/(e0+e1+e2);
            P[137]=e0*inv; P[138]=e1*inv; P[139]=e2*inv;
        }
        __syncthreads();
        if (tid < 64) {
            sh[S_KEY + 2*tid]     = co[64 + tid]  * scal[0];   // packed keys
            sh[S_KEY + 2*tid + 1] = co[134 + tid] * scal[1];
            P[140 + tid] = sigmoidf(co[204 + tid]);   // e
            P[204 + tid] = co[268 + tid];             // a
            const float o = co[tid];
            sh[S_COX + t*CO + tid] = o;               // persist out_t (row consumed)
            if (chunk == 0) dout[(t*BB + b)*OUTS + tid] = o;
        }
        __syncthreads();

        if (t == TT - 1) break;    // last output emitted; remaining phases moot

        // ===== Phase 2 (fused, 512-thr): lazy update + cosine similarity ====
        {
            const float beta_r = P[128], beta_w = P[134];
            const int l = tid;
            const float wn = sh[S_WWN + l];
            float dr = 0.f, dw = 0.f, ds = 0.f;
            #pragma unroll 16
            for (int w = 0; w < WW; ++w) {
                float m = sh[S_MEM + w*CHUNK + l];
                const float2 ea = *(const float2*)(sh + S_EAP + 2*w);
                m = fmaf(wn, fmaf(-m, ea.x, ea.y), m);   // lazy write (t-1)
                sh[S_MEM + w*CHUNK + l] = m;
                const float2 kk = *(const float2*)(sh + S_KEY + 2*w);
                dr = fmaf(m, kk.x, dr);
                dw = fmaf(m, kk.y, dw);
                ds = fmaf(m, m, ds);
            }
            const float inm = rsqrtf(ds + 1e-14f);
            const float er = __expf(dr*inm - beta_r);   // arg in [-2b, 0]
            const float ew = __expf(dw*inm - beta_w);
            sh[S_ER + l] = er; sh[S_EW + l] = ew;
            float se = er, sw = ew;
            #pragma unroll
            for (int o = 16; o; o >>= 1) {
                se += __shfl_xor_sync(0xffffffffu, se, o);
                sw += __shfl_xor_sync(0xffffffffu, sw, o);
            }
            if (lane == 0) { sh[S_SCR + warp] = se; sh[S_SCR + 16 + warp] = sw; }
            __syncthreads();
            if (tid == 0) {
                float a = 0.f, c = 0.f;
                #pragma unroll
                for (int i = 0; i < 16; ++i) { a += sh[S_SCR+i]; c += sh[S_SCR+16+i]; }
                stcg_f4(&g_val2[b][chunk][0],
                        make_float4(a, c, sh[S_ER+0], sh[S_ER+CHUNK-1]));
                stcg_f4(&g_val2[b][chunk][4],
                        make_float4(sh[S_EW+0], sh[S_EW+CHUNK-1], 0.f, 0.f));
                __threadfence();
                stcg_u(&g_tick2[b][chunk], (unsigned)(t+1));
            }
        }

        // ===== Phase 3: gate + shift + sharpen; post sums+halos EARLY =====
        poll8(g_tick2[b], (unsigned)(t+1), tid);
        if (tid < 8) {
            float se  = ldcg_f(&g_val2[b][tid][0]);
            float sw2 = ldcg_f(&g_val2[b][tid][1]);
            #pragma unroll
            for (int o = 4; o; o >>= 1) {
                se  += __shfl_xor_sync(0xffu, se,  o, 8);
                sw2 += __shfl_xor_sync(0xffu, sw2, o, 8);
            }
            if (tid == 0) { sh[S_SCR + 40] = se; sh[S_SCR + 41] = sw2; }
        }
        __syncthreads();
        {
            const float inv_ser = 1.f / sh[S_SCR + 40];
            const float inv_sew = 1.f / sh[S_SCR + 41];
            const float inv_srp = P[280];   // prev-step normalizers
            const float inv_swp = P[281];
            const float gr  = P[129], gamr = P[130];
            const float sr0 = P[131], sr1 = P[132], sr2 = P[133];
            const float gw  = P[135], gamw = P[136];
            const float sw0 = P[137], sw1 = P[138], sw2 = P[139];
            const int prv = (chunk + 7) & 7, nxt = (chunk + 1) & 7;
            const int k = tid;
            float cmr, cmw, pmr, pmw, cpr, cpw, ppr, ppw;
            if (k == 0) {
                cmr = ldcg_f(&g_val2[b][prv][3]); cmw = ldcg_f(&g_val2[b][prv][5]);
                pmr = ldcg_f(&g_val3[pb][b][prv][3]) * inv_srp;
                pmw = ldcg_f(&g_val3[pb][b][prv][5]) * inv_swp;
            } else {
                cmr = sh[S_ER + k-1];  cmw = sh[S_EW + k-1];
                pmr = sh[S_SWR + k-1]; pmw = sh[S_SWW + k-1];
            }
            if (k == CHUNK-1) {
                cpr = ldcg_f(&g_val2[b][nxt][2]); cpw = ldcg_f(&g_val2[b][nxt][4]);
                ppr = ldcg_f(&g_val3[pb][b][nxt][2]) * inv_srp;
                ppw = ldcg_f(&g_val3[pb][b][nxt][4]) * inv_swp;
            } else {
                cpr = sh[S_ER + k+1];  cpw = sh[S_EW + k+1];
                ppr = sh[S_SWR + k+1]; ppw = sh[S_SWW + k+1];
            }
            const float ccr = sh[S_ER + k],  pcr = sh[S_SWR + k];
            const float ccw = sh[S_EW + k],  pcw = sh[S_SWW + k];
            float wgm = cmr*inv_ser*gr + (1.f-gr)*pmr;
            float wgc = ccr*inv_ser*gr + (1.f-gr)*pcr;
            float wgp = cpr*inv_ser*gr + (1.f-gr)*ppr;
            const float wur = powf(fmaxf(sr0*wgm + sr1*wgc + sr2*wgp, 0.f), gamr);
            wgm = cmw*inv_sew*gw + (1.f-gw)*pmw;
            wgc = ccw*inv_sew*gw + (1.f-gw)*pcw;
            wgp = cpw*inv_sew*gw + (1.f-gw)*ppw;
            const float wuw = powf(fmaxf(sw0*wgm + sw1*wgc + sw2*wgp, 0.f), gamw);
            sh[S_WUR + k] = wur; sh[S_WUW + k] = wuw;
            float ps_r = wur, ps_w = wuw;
            #pragma unroll
            for (int o = 16; o; o >>= 1) {
                ps_r += __shfl_xor_sync(0xffffffffu, ps_r, o);
                ps_w += __shfl_xor_sync(0xffffffffu, ps_w, o);
            }
            if (lane == 0) { sh[S_SCR + warp] = ps_r; sh[S_SCR + 16 + warp] = ps_w; }
            __syncthreads();
            if (tid == 0) {
                float a = 0.f, c = 0.f;
                #pragma unroll
                for (int i = 0; i < 16; ++i) { a += sh[S_SCR+i]; c += sh[S_SCR+16+i]; }
                float* v3 = &g_val3[t & 1][b][chunk][0];
                stcg_f4(v3,     make_float4(a, c, sh[S_WUR+0], sh[S_WUR+CHUNK-1]));
                stcg_f4(v3 + 4, make_float4(sh[S_WUW+0], sh[S_WUW+CHUNK-1], 0.f, 0.f));
                __threadfence();
                stcg_u(&g_tick3[b][chunk], (unsigned)(t+1));
            }
        }

        // ===== Phase 4a: UNNORMALIZED r-partials, post tick4 (hides tick3) ==
        {
            float racc[4] = {0.f, 0.f, 0.f, 0.f};
            const int wbase = warp * 4;
            #pragma unroll
            for (int kk = 0; kk < 4; ++kk) {
                const int j = lane + 32*kk;
                const float4 r = *(const float4*)(sh + S_WUR + 4*j);
                #pragma unroll
                for (int w = 0; w < 4; ++w) {
                    const float4 m = *(const float4*)(sh + S_MEM + (wbase+w)*CHUNK + 4*j);
                    racc[w] += m.x*r.x + m.y*r.y + m.z*r.z + m.w*r.w;
                }
            }
            #pragma unroll
            for (int w = 0; w < 4; ++w) {
                #pragma unroll
                for (int o = 16; o; o >>= 1)
                    racc[w] += __shfl_xor_sync(0xffffffffu, racc[w], o);
                if (lane == 0) sh[S_SCR + 64 + wbase + w] = racc[w];
            }
        }
        __syncthreads();
        if (tid < 16) {
            const float4 v = *(const float4*)(sh + S_SCR + 64 + 4*tid);
            stcg_f4(&g_val4[b][chunk][16 + 4*tid], v);
            __threadfence();
        }
        __syncthreads();
        if (tid == 0) stcg_u(&g_tick4[b][chunk], (unsigned)(t+1));

        // ===== Phase 4b: poll tick3 (likely ready), normalize, set pending ==
        poll8(g_tick3[b], (unsigned)(t+1), tid);
        if (tid < 8) {
            float sr  = ldcg_f(&g_val3[t & 1][b][tid][0]);
            float sw3 = ldcg_f(&g_val3[t & 1][b][tid][1]);
            #pragma unroll
            for (int o = 4; o; o >>= 1) {
                sr  += __shfl_xor_sync(0xffu, sr,  o, 8);
                sw3 += __shfl_xor_sync(0xffu, sw3, o, 8);
            }
            if (tid == 0) {
                P[280] = 1.f / sr;    // inv_sr (used next step)
                P[281] = 1.f / sw3;   // inv_sw
            }
        }
        __syncthreads();
        {
            const float inv_sr = P[280];
            const float inv_sw = P[281];
            const float wn = sh[S_WUW + tid] * inv_sw;
            sh[S_SWR + tid] = sh[S_WUR + tid] * inv_sr;   // w_prev (read head)
            sh[S_SWW + tid] = wn;                          // w_prev (write head)
            sh[S_WWN + tid] = wn;                          // pending update weight
            if (tid < 64) {                                // pending e,a (step t)
                sh[S_EAP + 2*tid]     = P[140 + tid];
                sh[S_EAP + 2*tid + 1] = P[204 + tid];
            }
        }
        __syncthreads();
    }
}

extern "C" void kernel_launch(void* const* d_in, const int* in_sizes, int n_in,
                              void* d_out, int out_size) {
    const float* x  = (const float*)d_in[0];   // (T,B,IN) fp32
    const float* Wc = (const float*)d_in[1];   // (192,332) fp32
    const float* bc = (const float*)d_in[2];   // (332,)   fp32
    static bool attr_done = false;
    if (!attr_done) {
        cudaFuncSetAttribute(ntm_kernel, cudaFuncAttributeMaxDynamicSharedMemorySize,
                             S_TOT * sizeof(float));
        attr_done = true;
    }
    ntm_kernel<<<NBLK, NTHR, S_TOT * sizeof(float)>>>(x, Wc, bc, (float*)d_out);
}